// round 9
// baseline (speedup 1.0000x reference)
#include <cuda_runtime.h>
#include <cstdint>

// ConcatenateMeanMax split into two kernels:
//   A: out[b][0:128]   = bond_ft[b]                  (pure stream copy)
//   B: out[b][128:256] = mean(atom[s0], atom[s1])    (gather + reduce)
//      out[b][256:384] = max (atom[s0], atom[s1])
//
// Rationale (measured over R1-R8): fused kernel is stuck at 1.03 GB DRAM
// (925 MB floor) because the bond-read + output-store streams churn L2 and
// hold the 102.4 MB atom table to ~50% hit rate on its ~4x reuse. Splitting
// removes 2/3 of the L2 churn from the gather kernel. All once-through
// streams use .cs; atom gathers use default caching.

constexpr int D  = 128;
constexpr int DV = D / 4;   // 32 float4 per row
constexpr int OV = 3 * DV;  // 96 float4 per output row

// ---- Kernel A: strided copy bond_ft -> out[:, 0:128] -------------------
__global__ __launch_bounds__(256)
void copy_bond_kernel(const float4* __restrict__ bond_ft,
                      float4* __restrict__ out,
                      long long n_f4)          // n_bonds * 32
{
    const long long i = (long long)blockIdx.x * blockDim.x + threadIdx.x;
    if (i >= n_f4) return;
    const long long bond = i >> 5;       // i / 32
    const int       col  = (int)(i & 31);
    const float4 v = __ldcs(&bond_ft[i]);            // coalesced read
    __stcs(&out[bond * OV + col], v);                // coalesced per-warp 512B
}

// ---- Kernel B: gather mean/max -> out[:, 128:384] ----------------------
__global__ __launch_bounds__(256)
void gather_mean_max_kernel(const float4* __restrict__ atom_ft,
                            const int2*  __restrict__ edge_src2,
                            float4* __restrict__ out,
                            int n_bonds)
{
    const int gwarp = (blockIdx.x * blockDim.x + threadIdx.x) >> 5;
    const int lane  = threadIdx.x & 31;
    if (gwarp >= n_bonds) return;

    const int2 s = __ldg(&edge_src2[gwarp]);

    // reused atom rows: default caching -> table stays resident in L2
    const float4 a0 = __ldg(&atom_ft[(long long)s.x * DV + lane]);
    const float4 a1 = __ldg(&atom_ft[(long long)s.y * DV + lane]);

    float4 mean_v, max_v;
    mean_v.x = (a0.x + a1.x) * 0.5f;  max_v.x = fmaxf(a0.x, a1.x);
    mean_v.y = (a0.y + a1.y) * 0.5f;  max_v.y = fmaxf(a0.y, a1.y);
    mean_v.z = (a0.z + a1.z) * 0.5f;  max_v.z = fmaxf(a0.z, a1.z);
    mean_v.w = (a0.w + a1.w) * 0.5f;  max_v.w = fmaxf(a0.w, a1.w);

    float4* orow = out + (long long)gwarp * OV;
    __stcs(orow + DV + lane,     mean_v);
    __stcs(orow + 2 * DV + lane, max_v);
}

extern "C" void kernel_launch(void* const* d_in, const int* in_sizes, int n_in,
                              void* d_out, int out_size)
{
    const float4* atom_ft  = (const float4*)d_in[0];   // [N_ATOMS, 128] f32
    const float4* bond_ft  = (const float4*)d_in[1];   // [N_BONDS, 128] f32
    const int2*   edge_src = (const int2*)d_in[2];     // [N_BONDS*2] i32 -> int2 per bond
    // d_in[3] = edge_dst (structurally repeat(arange, 2)) -- not needed.

    const int n_bonds = in_sizes[1] / D;

    // Kernel B first: gathers get a clean L2; copy kernel doesn't need one.
    {
        const int threads = 256;                 // 8 warps/block
        const int wpb = threads / 32;
        const int blocks = (n_bonds + wpb - 1) / wpb;
        gather_mean_max_kernel<<<blocks, threads>>>(
            atom_ft, edge_src, (float4*)d_out, n_bonds);
    }
    {
        const long long n_f4 = (long long)n_bonds * DV;
        const int threads = 256;
        const int blocks = (int)((n_f4 + threads - 1) / threads);
        copy_bond_kernel<<<blocks, threads>>>(bond_ft, (float4*)d_out, n_f4);
    }
}

// round 10
// speedup vs baseline: 1.1056x; 1.1056x over previous
#include <cuda_runtime.h>
#include <cstdint>

// ConcatenateMeanMax: out[b] = concat(bond_ft[b], mean(atom_ft[s0], atom_ft[s1]),
//                                     max(atom_ft[s0], atom_ft[s1]))
// DEG = 2 fixed (edge_dst is repeat(arange(n_bonds), 2)).
//
// CONVERGED CONFIG (best of 9 measured variants):
//   - one warp per bond, float4 per lane (512B per row, fully coalesced)
//   - fused single kernel: output row written contiguously (1536B) -> best
//     DRAM page locality (a split copy kernel measured 5.5 TB/s vs 6.6 fused)
//   - __ldcs bond (read-once, evict-first), __ldg atoms (reused, default),
//     __stcs out (write-once, streaming): 1.030 GB traffic @ 6.60 TB/s
//   Hint-matrix results: {plain,stcs,stwt}x{ldg,ldcs,ldcv} all measured;
//   ldcs+stcs is the traffic minimum. evict_last pinning requires the
//   persisting-L2 carveout, which the harness forbids.
// Practical roofline: 1.03 GB / ~6.6 TB/s mixed-stream ceiling ~= 156us ncu.

constexpr int D  = 128;
constexpr int DV = D / 4;  // 32 float4 per row

__global__ __launch_bounds__(256)
void concat_mean_max_kernel(const float4* __restrict__ atom_ft,
                            const float4* __restrict__ bond_ft,
                            const int2*  __restrict__ edge_src2,
                            float4* __restrict__ out,
                            int n_bonds)
{
    const int gwarp = (blockIdx.x * blockDim.x + threadIdx.x) >> 5;
    const int lane  = threadIdx.x & 31;
    if (gwarp >= n_bonds) return;

    const int2 s = __ldg(&edge_src2[gwarp]);

    // gathers first: longest-latency (L2-miss-prone) accesses head the queue
    const float4 a0 = __ldg(&atom_ft[(long long)s.x * DV + lane]);
    const float4 a1 = __ldg(&atom_ft[(long long)s.y * DV + lane]);

    // read-once bond row: evict-first
    const float4 bf = __ldcs(&bond_ft[(long long)gwarp * DV + lane]);

    float4 mean_v, max_v;
    mean_v.x = (a0.x + a1.x) * 0.5f;  max_v.x = fmaxf(a0.x, a1.x);
    mean_v.y = (a0.y + a1.y) * 0.5f;  max_v.y = fmaxf(a0.y, a1.y);
    mean_v.z = (a0.z + a1.z) * 0.5f;  max_v.z = fmaxf(a0.z, a1.z);
    mean_v.w = (a0.w + a1.w) * 0.5f;  max_v.w = fmaxf(a0.w, a1.w);

    float4* orow = out + (long long)gwarp * (3 * DV);
    // write-once output: streaming stores, contiguous 1536B per bond row
    __stcs(orow + lane,          bf);
    __stcs(orow + DV + lane,     mean_v);
    __stcs(orow + 2 * DV + lane, max_v);
}

extern "C" void kernel_launch(void* const* d_in, const int* in_sizes, int n_in,
                              void* d_out, int out_size)
{
    const float4* atom_ft  = (const float4*)d_in[0];   // [N_ATOMS, 128] f32
    const float4* bond_ft  = (const float4*)d_in[1];   // [N_BONDS, 128] f32
    const int2*   edge_src = (const int2*)d_in[2];     // [N_BONDS*2] i32 -> int2 per bond
    // d_in[3] = edge_dst (structurally repeat(arange, 2)) -- not needed.

    const int n_bonds = in_sizes[1] / D;

    const int threads = 256;                 // 8 warps/block
    const int warps_per_block = threads / 32;
    const int blocks = (n_bonds + warps_per_block - 1) / warps_per_block;

    concat_mean_max_kernel<<<blocks, threads>>>(
        atom_ft, bond_ft, edge_src, (float4*)d_out, n_bonds);
}